// round 2
// baseline (speedup 1.0000x reference)
#include <cuda_runtime.h>

#define NTOK 4096
#define CDIM 256
#define HEADS 8
#define DHEAD 32
#define MASK_NEGF (-9.0e15f)

// scratch (allocation-free rule: device globals)
__device__ float g_qkv[NTOK * 3 * CDIM];   // [N, 3*C]  (q|k|v per token)
__device__ float g_att[NTOK * CDIM];       // attention output [N, C]

// ---------------------------------------------------------------------------
// GEMM: Y[m][n] = sum_k A[m][k] * B[n][k]  (+ bias[n])   A:[M,K] B:[Nn,K]
// 64x64 tile, 256 threads, 4x4 microtile, K-step 16, k-major smem.
// ---------------------------------------------------------------------------
__global__ __launch_bounds__(256) void gemm_nt(
    const float* __restrict__ A, const float* __restrict__ B,
    const float* __restrict__ bias, float* __restrict__ Y,
    int M, int Nn, int K)
{
    __shared__ float As[16][68];
    __shared__ float Bs[16][68];

    const int tid = threadIdx.x;
    const int tx = tid & 15;
    const int ty = tid >> 4;
    const int m0 = blockIdx.y << 6;
    const int n0 = blockIdx.x << 6;

    const int lr = tid >> 2;          // 0..63
    const int lk = (tid & 3) << 2;    // 0,4,8,12

    const float* Ap = A + (size_t)(m0 + lr) * K + lk;
    const float* Bp = B + (size_t)(n0 + lr) * K + lk;

    float c[4][4];
#pragma unroll
    for (int i = 0; i < 4; i++)
#pragma unroll
        for (int j = 0; j < 4; j++) c[i][j] = 0.0f;

    for (int k0 = 0; k0 < K; k0 += 16) {
        float4 av = *(const float4*)(Ap + k0);
        float4 bv = *(const float4*)(Bp + k0);
        __syncthreads();
        As[lk + 0][lr] = av.x; As[lk + 1][lr] = av.y;
        As[lk + 2][lr] = av.z; As[lk + 3][lr] = av.w;
        Bs[lk + 0][lr] = bv.x; Bs[lk + 1][lr] = bv.y;
        Bs[lk + 2][lr] = bv.z; Bs[lk + 3][lr] = bv.w;
        __syncthreads();
#pragma unroll
        for (int kk = 0; kk < 16; kk++) {
            float4 a = *(const float4*)&As[kk][ty << 2];
            float4 b = *(const float4*)&Bs[kk][tx << 2];
            c[0][0] += a.x * b.x; c[0][1] += a.x * b.y; c[0][2] += a.x * b.z; c[0][3] += a.x * b.w;
            c[1][0] += a.y * b.x; c[1][1] += a.y * b.y; c[1][2] += a.y * b.z; c[1][3] += a.y * b.w;
            c[2][0] += a.z * b.x; c[2][1] += a.z * b.y; c[2][2] += a.z * b.z; c[2][3] += a.z * b.w;
            c[3][0] += a.w * b.x; c[3][1] += a.w * b.y; c[3][2] += a.w * b.z; c[3][3] += a.w * b.w;
        }
    }

    float b0 = 0.f, b1 = 0.f, b2 = 0.f, b3 = 0.f;
    if (bias) {
        const int nb = n0 + (tx << 2);
        b0 = bias[nb + 0]; b1 = bias[nb + 1]; b2 = bias[nb + 2]; b3 = bias[nb + 3];
    }
#pragma unroll
    for (int i = 0; i < 4; i++) {
        const int mrow = m0 + (ty << 2) + i;
        float4 o;
        o.x = c[i][0] + b0; o.y = c[i][1] + b1;
        o.z = c[i][2] + b2; o.w = c[i][3] + b3;
        *(float4*)(Y + (size_t)mrow * Nn + n0 + (tx << 2)) = o;
    }
}

// ---------------------------------------------------------------------------
// Flash attention, fp32. Block = 64 query rows x 1 head, 128 threads.
// Thread pair (tid, tid^1) shares one query row: half=tid&1 owns 32 of the
// 64 keys of each tile; each thread accumulates its keys over ALL 32 dh and
// the partials are combined once at the end via shfl.
// Scale (1/sqrt(32)) is folded into q at load; softmax runs in base-2
// (scores pre-multiplied by log2(e)) so exp() is a bare MUFU.EX2.
// ---------------------------------------------------------------------------
__global__ __launch_bounds__(128, 4) void attn_kernel(
    const float* __restrict__ qkv, const int* __restrict__ adj,
    float* __restrict__ out)
{
    __shared__ float Ks[64][36];  // stride 36 to spread store banks
    __shared__ float Vs[64][36];

    const int tid = threadIdx.x;
    const int ql = tid >> 1;
    const int half = tid & 1;
    const int qg = (blockIdx.x << 6) + ql;
    const int h = blockIdx.y;
    // q pre-scale: (1/sqrt(32)) * log2(e)  -> scores already in log2 domain
    const float qscale = 0.17677669529663687f * 1.4426950408889634f;

    // query row -> registers (both pair threads hold full row), pre-scaled
    float qreg[DHEAD];
    {
        const float4* qp4 = (const float4*)(qkv + (size_t)qg * 768 + h * DHEAD);
#pragma unroll
        for (int i = 0; i < 8; i++) {
            float4 t = qp4[i];
            qreg[4 * i + 0] = t.x * qscale; qreg[4 * i + 1] = t.y * qscale;
            qreg[4 * i + 2] = t.z * qscale; qreg[4 * i + 3] = t.w * qscale;
        }
    }

    float m = MASK_NEGF;
    float l = 0.0f;
    float acc[DHEAD];
#pragma unroll
    for (int d = 0; d < DHEAD; d++) acc[d] = 0.0f;

    const int lr = tid >> 1;          // tile row this thread loads
    const int lc = (tid & 1) * 16;    // 16-float chunk
    const int kbase = half * 32;      // this thread's key subset within tile

    for (int kt = 0; kt < NTOK; kt += 64) {
        __syncthreads();
        {
            const float* kp = qkv + (size_t)(kt + lr) * 768 + CDIM + h * DHEAD + lc;
            const float* vp = kp + CDIM;
            const float4* kp4 = (const float4*)kp;
            const float4* vp4 = (const float4*)vp;
            float4 k0 = kp4[0], k1 = kp4[1], k2 = kp4[2], k3 = kp4[3];
            float4 v0 = vp4[0], v1 = vp4[1], v2 = vp4[2], v3 = vp4[3];
            *(float4*)&Ks[lr][lc + 0]  = k0;
            *(float4*)&Ks[lr][lc + 4]  = k1;
            *(float4*)&Ks[lr][lc + 8]  = k2;
            *(float4*)&Ks[lr][lc + 12] = k3;
            *(float4*)&Vs[lr][lc + 0]  = v0;
            *(float4*)&Vs[lr][lc + 4]  = v1;
            *(float4*)&Vs[lr][lc + 8]  = v2;
            *(float4*)&Vs[lr][lc + 12] = v3;
        }
        __syncthreads();

        // S = q . K^T for this thread's 32 keys (already log2-domain scaled)
        float s[32];
#pragma unroll
        for (int k = 0; k < 32; k++) s[k] = 0.0f;
#pragma unroll
        for (int d4 = 0; d4 < 8; d4++) {
            const float qx = qreg[4 * d4 + 0], qy = qreg[4 * d4 + 1];
            const float qz = qreg[4 * d4 + 2], qw = qreg[4 * d4 + 3];
#pragma unroll
            for (int k = 0; k < 32; k++) {
                float4 kv = *(const float4*)&Ks[kbase + k][4 * d4];
                s[k] += qx * kv.x + qy * kv.y + qz * kv.z + qw * kv.w;
            }
        }

        // mask (scores are log2-domain; MASK_NEGF stays a huge negative)
        {
            const int* arow = adj + (size_t)qg * NTOK + kt + kbase;
#pragma unroll
            for (int k4 = 0; k4 < 8; k4++) {
                int4 a4 = *(const int4*)(arow + 4 * k4);
                if (a4.x <= 0) s[4 * k4 + 0] = MASK_NEGF;
                if (a4.y <= 0) s[4 * k4 + 1] = MASK_NEGF;
                if (a4.z <= 0) s[4 * k4 + 2] = MASK_NEGF;
                if (a4.w <= 0) s[4 * k4 + 3] = MASK_NEGF;
            }
        }

        // online softmax in base-2 (pair-combined via shfl with lane tid^1)
        float mloc = s[0];
#pragma unroll
        for (int k = 1; k < 32; k++) mloc = fmaxf(mloc, s[k]);
        mloc = fmaxf(mloc, __shfl_xor_sync(0xffffffffu, mloc, 1));
        const float mnew = fmaxf(m, mloc);
        const float corr = exp2f(m - mnew);
        m = mnew;

        float ls = 0.0f;
#pragma unroll
        for (int k = 0; k < 32; k++) {
            float p = exp2f(s[k] - mnew);
            s[k] = p;
            ls += p;
        }
        ls += __shfl_xor_sync(0xffffffffu, ls, 1);
        l = l * corr + ls;

#pragma unroll
        for (int d = 0; d < DHEAD; d++) acc[d] *= corr;

        // acc += P . V  (this thread's keys, all 32 dh)
#pragma unroll
        for (int k = 0; k < 32; k++) {
            const float p = s[k];
#pragma unroll
            for (int d4 = 0; d4 < 8; d4++) {
                float4 vv = *(const float4*)&Vs[kbase + k][4 * d4];
                acc[4 * d4 + 0] += p * vv.x;
                acc[4 * d4 + 1] += p * vv.y;
                acc[4 * d4 + 2] += p * vv.z;
                acc[4 * d4 + 3] += p * vv.w;
            }
        }
    }

    // combine pair partials, normalize, store
    const float inv = 1.0f / l;
#pragma unroll
    for (int d = 0; d < DHEAD; d++) {
        float t = acc[d] + __shfl_xor_sync(0xffffffffu, acc[d], 1);
        acc[d] = t * inv;
    }
    float* op = out + (size_t)qg * CDIM + h * DHEAD;
    if (half == 0) {
#pragma unroll
        for (int j = 0; j < 4; j++) {
            float4 o; o.x = acc[4 * j]; o.y = acc[4 * j + 1];
            o.z = acc[4 * j + 2]; o.w = acc[4 * j + 3];
            *(float4*)(op + 4 * j) = o;
        }
    } else {
#pragma unroll
        for (int j = 4; j < 8; j++) {
            float4 o; o.x = acc[4 * j]; o.y = acc[4 * j + 1];
            o.z = acc[4 * j + 2]; o.w = acc[4 * j + 3];
            *(float4*)(op + 4 * j) = o;
        }
    }
}

// ---------------------------------------------------------------------------
extern "C" void kernel_launch(void* const* d_in, const int* in_sizes, int n_in,
                              void* d_out, int out_size)
{
    const float* x      = (const float*)d_in[0];
    const int*   adj    = (const int*)d_in[1];
    const float* w_qkv  = (const float*)d_in[2];
    const float* w_proj = (const float*)d_in[3];
    const float* b_proj = (const float*)d_in[4];
    float*       out    = (float*)d_out;

    void *p1 = nullptr, *p2 = nullptr;
    cudaGetSymbolAddress(&p1, g_qkv);
    cudaGetSymbolAddress(&p2, g_att);
    float* qkv = (float*)p1;
    float* att = (float*)p2;

    // 1) QKV projection: [4096, 768] = x [4096,256] @ w_qkv^T [256,768]
    {
        dim3 grid(768 / 64, NTOK / 64);
        gemm_nt<<<grid, 256>>>(x, w_qkv, nullptr, qkv, NTOK, 3 * CDIM, CDIM);
    }
    // 2) masked flash attention per head
    {
        dim3 grid(NTOK / 64, HEADS);
        attn_kernel<<<grid, 128>>>(qkv, adj, att);
    }
    // 3) output projection + bias
    {
        dim3 grid(CDIM / 64, NTOK / 64);
        gemm_nt<<<grid, 256>>>(att, w_proj, b_proj, out, NTOK, CDIM, CDIM);
    }
}